// round 13
// baseline (speedup 1.0000x reference)
#include <cuda_runtime.h>
#include <stdint.h>

#define NUM_NODES 100000
#define NUM_EDGES 400000
#define MAXR      24          // safety bound; convergence ~12-17 rounds
#define BLOCKS    148         // 1 block/SM (validated best config)
#define TPB       1024
#define NT        (BLOCKS * TPB)

typedef unsigned long long u64;

// Scratch (__device__ globals; no allocs). Cross-replay invariant:
// g_best == 0 and g_any == 0 at entry (end-of-replay clear below;
// g_dead / labels / keys are re-initialized in the fused round-0 phase).
__device__ u64           g_key[NUM_EDGES];    // 51-bit key: score32<<19 | (524287-e)
__device__ int           g_label[NUM_NODES];
__device__ u64           g_best[NUM_NODES];   // tagged: (round+1)<<51 | key51
__device__ unsigned char g_dead[NUM_EDGES];   // 1 = endpoints share a component
__device__ int           g_any[MAXR];         // any live edge found in round r's A
__device__ unsigned      g_count = 0;         // barrier arrivals
__device__ unsigned      g_gen   = 0;         // barrier generation (wrap-safe)

#define ALLDEAD 0x0101010101010101ULL

// ---- software grid barrier (R2-validated: nanosleep spin) ----
__device__ __forceinline__ unsigned ld_acq(const unsigned* p) {
    unsigned v;
    asm volatile("ld.acquire.gpu.u32 %0, [%1];" : "=r"(v) : "l"(p) : "memory");
    return v;
}
__device__ __forceinline__ void st_rel(unsigned* p, unsigned v) {
    asm volatile("st.release.gpu.u32 [%0], %1;" :: "l"(p), "r"(v) : "memory");
}
__device__ __forceinline__ void gbar() {
    __syncthreads();
    if (threadIdx.x == 0) {
        unsigned my = ld_acq(&g_gen);
        __threadfence();
        unsigned a = atomicAdd(&g_count, 1u);
        if (a == BLOCKS - 1) {
            g_count = 0;
            __threadfence();
            st_rel(&g_gen, my + 1u);
        } else {
            while (ld_acq(&g_gen) == my) __nanosleep(32);
        }
    }
    __syncthreads();
}

// read-only chase to root. Safe concurrently with flatten writes: every
// label write (flatten shortcut) points toward the stable root, and the
// hook digraph is acyclic (mutual 2-cycles broken by id in phase B).
__device__ __forceinline__ int find_ro(int v) {
    int p = g_label[v];
    #pragma unroll 1
    while (true) {
        int q = g_label[p];
        if (q == p) return p;
        p = q;
    }
}

__global__ void __launch_bounds__(TPB, 1)
boruvka_kernel(const float* __restrict__ s,
               const float* __restrict__ u,
               const int*   __restrict__ src,
               const int*   __restrict__ dst,
               float*       __restrict__ out)
{
    const int tid = blockIdx.x * TPB + threadIdx.x;

    // ========== fused init + round-0 best (labels are identity) ==========
    // Keys bitwise-match the JAX f32 pipeline (validated rel_err==0.0):
    //   score = 1/(1+expf(-s)) + (-logf(-logf(u+1e-9)+1e-9))
    {
        const u64 tag0 = 1ULL << 51;
        for (int e = tid; e < NUM_EDGES; e += NT) {
            float sp = 1.0f / (1.0f + expf(-s[e]));
            float gb = -logf(-logf(u[e] + 1e-9f) + 1e-9f);
            unsigned ub = __float_as_uint(sp + gb);
            ub = (ub & 0x80000000u) ? ~ub : (ub | 0x80000000u);  // order-preserving
            u64 key = ((u64)ub << 19) | (u64)(524287 - e);       // ties -> lowest idx
            g_key[e] = key;
            out[e] = 0.0f;
            int ra = src[e], rb = dst[e];
            if (ra != rb) {
                g_dead[e] = 0;
                u64 kv = tag0 | key;
                atomicMax(&g_best[ra], kv);
                atomicMax(&g_best[rb], kv);
            } else {
                g_dead[e] = 1;     // self-loop: dead forever
            }
        }
        for (int i = tid; i < NUM_NODES; i += NT) g_label[i] = i;
    }
    gbar();

    // ========== rounds: [hook] barrier [flatten+best] barrier ==========
    const unsigned* __restrict__ best_hi = ((const unsigned*)g_best) + 1;
    int r = 0;
    while (true) {
        // ---- slot 1, phase B: hook. Labels are FLAT here (identity at r=0,
        // else fully flattened by the previous CA slot), and hooks only write
        // label[root], so lu/lv are exactly the two distinct roots of e. ----
        {
            const unsigned mytag = (unsigned)(r + 1);
            for (int i = tid; i < NUM_NODES; i += NT) {
                // cheap tag check on the high word (tag = bits 63:51 -> hi>>19)
                if ((best_hi[2 * i] >> 19) != mytag) continue;
                u64 bk = g_best[i];
                int e  = 524287 - (int)(bk & 0x7FFFFULL);
                int lu = g_label[src[e]];
                int lv = g_label[dst[e]];
                int other = lu ^ lv ^ i;             // the other root
                if (g_best[other] == bk) {
                    // mutual 2-cycle (keys unique -> longer cycles impossible):
                    // only the larger-id root hooks; edge marked exactly once
                    if (i > other) { g_label[i] = other; out[e] = 1.0f; }
                } else {
                    g_label[i] = other; out[e] = 1.0f;
                }
            }
        }
        gbar();
        if (++r >= MAXR) break;         // safety (never hit)

        // ---- slot 2, merged phase C+A ----
        // C-part: flatten this thread's node chunk (parallel chases; writes
        // shortcut toward stable roots). By slot end ALL nodes are flat.
        for (int i = tid; i < NUM_NODES; i += NT) {
            int v = g_label[i];
            int p = g_label[v];
            #pragma unroll 1
            while (p != v) { v = p; p = g_label[v]; }
            g_label[i] = v;
        }
        // A-part: per-component best over live edges (read-only chases are
        // correct even while other blocks are still flattening).
        {
            const u64 tag = ((u64)(r + 1)) << 51;
            bool live_any = false;
            if (r < 3) {
                // early rounds: mostly live -> flat per-edge scan
                for (int e = tid; e < NUM_EDGES; e += NT) {
                    if (g_dead[e]) continue;
                    int lu = find_ro(src[e]);
                    int lv = find_ro(dst[e]);
                    if (lu == lv) { g_dead[e] = 1; continue; }
                    live_any = true;
                    u64 kv = tag | g_key[e];
                    atomicMax(&g_best[lu], kv);
                    atomicMax(&g_best[lv], kv);
                }
            } else {
                // late rounds: mostly dead -> 8-packed group skip
                const u64* dead8 = (const u64*)g_dead;          // 400000 % 8 == 0
                for (int g = tid; g < NUM_EDGES / 8; g += NT) {
                    u64 d8 = dead8[g];
                    if (d8 == ALLDEAD) continue;
                    int base = g * 8;
                    #pragma unroll 1
                    for (int j = 0; j < 8; ++j) {
                        if ((d8 >> (8 * j)) & 1) continue;
                        int e  = base + j;
                        int lu = find_ro(src[e]);
                        int lv = find_ro(dst[e]);
                        if (lu == lv) { g_dead[e] = 1; continue; }  // owner-thread store
                        live_any = true;
                        u64 kv = tag | g_key[e];
                        atomicMax(&g_best[lu], kv);
                        atomicMax(&g_best[lv], kv);
                    }
                }
            }
            if (live_any) g_any[r] = 1;   // idempotent racy store (validated pattern)
        }
        gbar();
        // zero live edges -> no best carries tag r+1 -> next B would be empty
        if (!g_any[r]) break;
    }

    // ---- end-of-replay clear (stream order covers the next replay) ----
    for (int i = tid; i < NUM_NODES; i += NT) g_best[i] = 0ULL;
    if (tid < MAXR) g_any[tid] = 0;
}

extern "C" void kernel_launch(void* const* d_in, const int* in_sizes, int n_in,
                              void* d_out, int out_size)
{
    const float* s   = (const float*)d_in[0];
    const float* u   = (const float*)d_in[1];
    const int*   ei  = (const int*)d_in[2];   // [2, E] row-major
    const int*   src = ei;
    const int*   dst = ei + NUM_EDGES;
    float*       out = (float*)d_out;

    boruvka_kernel<<<BLOCKS, TPB>>>(s, u, src, dst, out);
}

// round 14
// speedup vs baseline: 1.1673x; 1.1673x over previous
#include <cuda_runtime.h>
#include <stdint.h>

#define NUM_NODES 100000
#define NUM_EDGES 400000
#define MAXR      24          // safety bound; convergence ~17 rounds
#define BLOCKS    148         // 1 block/SM (validated best config)
#define TPB       1024
#define NT        (BLOCKS * TPB)

typedef unsigned long long u64;

// Scratch (__device__ globals; no allocs). Cross-replay invariant:
// g_best == 0 and g_any == 0 at entry (end-of-replay clear below;
// g_dead / g_sd / labels / keys are re-initialized in the fused round-0 phase).
__device__ u64           g_key[NUM_EDGES];    // 51-bit key: score32<<19 | (524287-e)
__device__ int2          g_sd[NUM_EDGES];     // packed (src,dst)
__device__ int           g_label[NUM_NODES];
__device__ u64           g_best[NUM_NODES];   // tagged: (round+1)<<51 | key51
__device__ unsigned char g_dead[NUM_EDGES];   // 1 = endpoints share a component
__device__ int           g_any[MAXR];         // any live edge in round r's A-part
__device__ unsigned      g_count = 0;         // barrier arrivals
__device__ unsigned      g_gen   = 0;         // barrier generation (wrap-safe)

// ---- software grid barrier (lean: release-atomic arrival) ----
__device__ __forceinline__ unsigned ld_acq(const unsigned* p) {
    unsigned v;
    asm volatile("ld.acquire.gpu.u32 %0, [%1];" : "=r"(v) : "l"(p) : "memory");
    return v;
}
__device__ __forceinline__ void st_rel(unsigned* p, unsigned v) {
    asm volatile("st.release.gpu.u32 [%0], %1;" :: "l"(p), "r"(v) : "memory");
}
__device__ __forceinline__ void gbar() {
    __syncthreads();
    if (threadIdx.x == 0) {
        unsigned my = ld_acq(&g_gen);
        unsigned a;
        // release-add: orders this block's pre-barrier writes (made visible to
        // this thread by the bar.sync above) before the arrival is observed
        asm volatile("atom.add.release.gpu.u32 %0, [%1], 1;"
                     : "=r"(a) : "l"(&g_count) : "memory");
        if (a == BLOCKS - 1) {
            g_count = 0;                     // ordered by the st.release below
            st_rel(&g_gen, my + 1u);
        } else {
            while (ld_acq(&g_gen) == my) __nanosleep(32);
        }
    }
    __syncthreads();
}

// read-only chase to root. Safe concurrently with flatten writes: every
// label write (flatten shortcut) points toward the stable root, and the
// hook digraph is acyclic (mutual 2-cycles broken by id in phase B).
__device__ __forceinline__ int find_ro(int v) {
    int p = g_label[v];
    #pragma unroll 1
    while (true) {
        int q = g_label[p];
        if (q == p) return p;
        p = q;
    }
}

__global__ void __launch_bounds__(TPB, 1)
boruvka_kernel(const float* __restrict__ s,
               const float* __restrict__ u,
               const int*   __restrict__ src,
               const int*   __restrict__ dst,
               float*       __restrict__ out)
{
    const int tid = blockIdx.x * TPB + threadIdx.x;

    // ========== fused init + round-0 best (labels are identity) ==========
    // Keys bitwise-match the JAX f32 pipeline (validated rel_err==0.0):
    //   score = 1/(1+expf(-s)) + (-logf(-logf(u+1e-9)+1e-9))
    {
        const u64 tag0 = 1ULL << 51;
        for (int e = tid; e < NUM_EDGES; e += NT) {
            float sp = 1.0f / (1.0f + expf(-s[e]));
            float gb = -logf(-logf(u[e] + 1e-9f) + 1e-9f);
            unsigned ub = __float_as_uint(sp + gb);
            ub = (ub & 0x80000000u) ? ~ub : (ub | 0x80000000u);  // order-preserving
            u64 key = ((u64)ub << 19) | (u64)(524287 - e);       // ties -> lowest idx
            g_key[e] = key;
            out[e] = 0.0f;
            int ra = src[e], rb = dst[e];
            g_sd[e] = make_int2(ra, rb);
            if (ra != rb) {
                g_dead[e] = 0;
                u64 kv = tag0 | key;
                atomicMax(&g_best[ra], kv);
                atomicMax(&g_best[rb], kv);
            } else {
                g_dead[e] = 1;     // self-loop: dead forever
            }
        }
        for (int i = tid; i < NUM_NODES; i += NT) g_label[i] = i;
    }
    gbar();

    // ========== rounds: [hook] barrier [flatten+best] barrier ==========
    int r = 0;
    while (true) {
        // ---- slot 1, phase B: hook. Labels are FLAT here (identity at r=0,
        // else fully flattened by the previous CA slot), and hooks only write
        // label[root], so lu/lv are exactly the two distinct roots of e. ----
        {
            const u64 mytag = (u64)(r + 1);
            for (int i = tid; i < NUM_NODES; i += NT) {
                u64 bk = g_best[i];
                if ((bk >> 51) != mytag) continue;   // stale tag / no live edge
                int e  = 524287 - (int)(bk & 0x7FFFFULL);
                int2 sd = g_sd[e];
                int lu = g_label[sd.x];
                int lv = g_label[sd.y];
                int other = lu ^ lv ^ i;             // the other root
                if (g_best[other] == bk) {
                    // mutual 2-cycle (keys unique -> longer cycles impossible):
                    // only the larger-id root hooks; edge marked exactly once
                    if (i > other) { g_label[i] = other; out[e] = 1.0f; }
                } else {
                    g_label[i] = other; out[e] = 1.0f;
                }
            }
        }
        gbar();
        if (++r >= MAXR) break;         // safety (never hit)

        // ---- slot 2, merged phase C+A ----
        // C-part: flatten this thread's node chunk (parallel chases; writes
        // shortcut toward stable roots). By slot end ALL nodes are flat.
        for (int i = tid; i < NUM_NODES; i += NT) {
            int v = g_label[i];
            int p = g_label[v];
            #pragma unroll 1
            while (p != v) { v = p; p = g_label[v]; }
            g_label[i] = v;
        }
        // A-part: per-component best over live edges, using read-only chases
        // (correct even while other blocks are still flattening).
        {
            const u64 tag = ((u64)(r + 1)) << 51;
            bool live_any = false;
            for (int e = tid; e < NUM_EDGES; e += NT) {
                if (g_dead[e]) continue;
                int2 sd = g_sd[e];
                int lu = find_ro(sd.x);
                int lv = find_ro(sd.y);
                if (lu == lv) { g_dead[e] = 1; continue; }   // dead forever
                live_any = true;
                u64 kv = tag | g_key[e];
                atomicMax(&g_best[lu], kv);
                atomicMax(&g_best[lv], kv);
            }
            if (live_any) g_any[r] = 1;   // idempotent racy store
        }
        gbar();
        // zero live edges -> no best carries tag r+1 -> next B provably empty
        if (!g_any[r]) break;
    }

    // ---- end-of-replay clear (stream order covers the next replay) ----
    for (int i = tid; i < NUM_NODES; i += NT) g_best[i] = 0ULL;
    if (tid < MAXR) g_any[tid] = 0;
}

extern "C" void kernel_launch(void* const* d_in, const int* in_sizes, int n_in,
                              void* d_out, int out_size)
{
    const float* s   = (const float*)d_in[0];
    const float* u   = (const float*)d_in[1];
    const int*   ei  = (const int*)d_in[2];   // [2, E] row-major
    const int*   src = ei;
    const int*   dst = ei + NUM_EDGES;
    float*       out = (float*)d_out;

    boruvka_kernel<<<BLOCKS, TPB>>>(s, u, src, dst, out);
}